// round 1
// baseline (speedup 1.0000x reference)
#include <cuda_runtime.h>
#include <cuda_bf16.h>
#include <math.h>

#define DIM   1280
#define NPAIR (DIM / 2)   // 640 sin/cos pairs per row

// Each block: 640 threads, thread t owns column-pair t (cols 2t, 2t+1).
// rate_t = 10000^(-2t/DIM) computed ONCE per thread (fp64 exp2 for accuracy),
// then the block strides over rows. Per row: broadcast-load time[b],
// Cody-Waite reduce mod 2pi, MUFU sin/cos, one float2 store (coalesced:
// threads 0..639 cover the whole 5120B row).
__global__ __launch_bounds__(NPAIR) void time_emb_kernel(
    const float* __restrict__ time,
    float* __restrict__ out,
    int batch)
{
    const int pair = threadIdx.x;  // 0..639

    // rate = exp2(-2 * pair * log2(10000) / DIM), computed in double so the
    // fp32-rounded result is within ~1 ulp of the reference's fp32 rate.
    const double K = -2.0 * 13.287712379549449 / (double)DIM;  // -2*log2(1e4)/DIM
    const float rate = (float)exp2((double)pair * K);

    // Cody-Waite constants for reduction mod 2*pi.
    // C1 = 6.28125 exact in fp32 with 7 mantissa bits -> q*C1 exact for q<=256.
    const float INV_2PI = 0.15915494309189535f;
    const float C1 = 6.28125f;
    const float C2 = 1.9353071795864769e-3f;  // 2*pi - C1 (fp32 rounded)

    float2* __restrict__ out2 = reinterpret_cast<float2*>(out);

    for (int b = blockIdx.x; b < batch; b += gridDim.x) {
        const float t = __ldg(time + b);          // broadcast within block
        const float ang = t * rate;               // up to ~1000 rad

        // reduce ang mod 2*pi -> r in [-pi, pi], abs err ~4e-8 rad
        const float q = rintf(ang * INV_2PI);     // |q| <= ~160
        float r = fmaf(q, -C1, ang);              // exact
        r = fmaf(q, -C2, r);

        const float s = __sinf(r);                // MUFU.SIN, |r|<=pi: err ~4e-7
        const float c = __cosf(r);                // MUFU.COS

        out2[(size_t)b * NPAIR + pair] = make_float2(s, c);
    }
}

extern "C" void kernel_launch(void* const* d_in, const int* in_sizes, int n_in,
                              void* d_out, int out_size)
{
    const float* time = (const float*)d_in[0];
    float* out = (float*)d_out;
    const int batch = in_sizes[0];  // 65536

    // 8 blocks/SM worth of work-stealing-free striding; 640 thr/block.
    int grid = 148 * 8;
    if (grid > batch) grid = batch;
    time_emb_kernel<<<grid, NPAIR>>>(time, out, batch);
}

// round 2
// speedup vs baseline: 2.0263x; 2.0263x over previous
#include <cuda_runtime.h>
#include <cuda_bf16.h>
#include <math.h>

#define DIM   1280
#define NVEC  (DIM / 4)   // 320 float4 per row; thread t owns pairs 2t, 2t+1

// Block: 320 threads. Thread t computes two rates once (fp64 exp2 for
// accuracy), then grid-strides over rows 4 at a time. Per iteration:
// 4 broadcast time loads up front (MLP), 16 MUFU sin/cos, 4 STG.128
// streaming stores. Warp covers 512 contiguous bytes per store.
__global__ __launch_bounds__(NVEC) void time_emb_kernel(
    const float* __restrict__ time,
    float4* __restrict__ out4,
    int batch)
{
    const int t = threadIdx.x;  // 0..319 -> pairs 2t, 2t+1

    // rate_k = 10000^(-2k/DIM) = exp2(k * K), K = -2*log2(1e4)/DIM.
    // fp64 exp2 keeps the fp32-rounded rate within ~1 ulp of reference.
    const double K = -2.0 * 13.287712379549449 / (double)DIM;
    const float rate0 = (float)exp2((double)(2 * t)     * K);
    const float rate1 = (float)exp2((double)(2 * t + 1) * K);

    // Cody-Waite mod-2pi: C1=6.28125 has 7 mantissa bits -> q*C1 exact, q<=256.
    const float INV_2PI = 0.15915494309189535f;
    const float C1 = 6.28125f;
    const float C2 = 1.9353071795864769e-3f;  // 2*pi - C1

    const int stride = gridDim.x << 2;
    for (int b = blockIdx.x << 2; b < batch; b += stride) {
        // Load 4 rows' timesteps up front (independent -> MLP).
        float tm[4];
        const int rem = batch - b;  // batch is 65536 (mult of 4), but be safe
        #pragma unroll
        for (int j = 0; j < 4; j++)
            tm[j] = (j < rem) ? __ldg(time + b + j) : 0.0f;

        #pragma unroll
        for (int j = 0; j < 4; j++) {
            if (j >= rem) break;

            const float a0 = tm[j] * rate0;
            const float a1 = tm[j] * rate1;

            const float q0 = rintf(a0 * INV_2PI);
            const float q1 = rintf(a1 * INV_2PI);
            float r0 = fmaf(q0, -C1, a0);  r0 = fmaf(q0, -C2, r0);
            float r1 = fmaf(q1, -C1, a1);  r1 = fmaf(q1, -C2, r1);

            float4 v;
            v.x = __sinf(r0);   // col 4t
            v.y = __cosf(r0);   // col 4t+1
            v.z = __sinf(r1);   // col 4t+2
            v.w = __cosf(r1);   // col 4t+3

            __stcs(out4 + (size_t)(b + j) * NVEC + t, v);  // streaming STG.128
        }
    }
}

extern "C" void kernel_launch(void* const* d_in, const int* in_sizes, int n_in,
                              void* d_out, int out_size)
{
    const float* time = (const float*)d_in[0];
    float4* out4 = (float4*)d_out;
    const int batch = in_sizes[0];  // 65536

    int grid = 2048;                         // 65536/(2048*4) = 8 iters/block
    int maxg = (batch + 3) / 4;
    if (grid > maxg) grid = maxg;
    time_emb_kernel<<<grid, NVEC>>>(time, out4, batch);
}